// round 3
// baseline (speedup 1.0000x reference)
#include <cuda_runtime.h>
#include <cuda_bf16.h>

#define SEQ   8192
#define DIN   256
#define H     2048
#define H4    8192
#define DOUT  64
#define NCTA  148
#define NTHR  448   // 14 warps
#define OUT_BASE (SEQ * DOUT)   // 524288

// ---------------- device scratch (allowed: __device__ globals) --------------
__device__ __nv_bfloat16 g_Whh[(size_t)H4 * H]; // 33.5 MB bf16 W_hh
__device__ float   g_xg [(size_t)SEQ * H4];     // 256 MB  x @ W_ih^T + b
__device__ float   g_hs [(size_t)SEQ * H];      // 64 MB   h history
__device__ float   g_hbuf[2][H];                // double-buffered h
__device__ float   g_WfcT[H * DOUT];            // W_fc transposed [k][d]
__device__ unsigned g_bar;                      // cumulative grid barrier

// ---------------- prep: bf16 convert, transpose, init ----------------------
__global__ void prep_kernel(const float* __restrict__ Whh,
                            const float* __restrict__ hprev,
                            const float* __restrict__ Wfc)
{
    size_t stride = (size_t)gridDim.x * blockDim.x;
    size_t i0 = (size_t)blockIdx.x * blockDim.x + threadIdx.x;
    // pairwise fp32 -> bf16x2
    const size_t npair = (size_t)H4 * H / 2;
    for (size_t p = i0; p < npair; p += stride) {
        float2 v = ((const float2*)Whh)[p];
        ((__nv_bfloat162*)g_Whh)[p] = __floats2bfloat162_rn(v.x, v.y);
    }
    for (size_t i = i0; i < H; i += stride)
        g_hbuf[0][i] = hprev[i];
    for (size_t i = i0; i < (size_t)H * DOUT; i += stride) {
        int d = (int)(i & (DOUT - 1));
        int k = (int)(i >> 6);
        g_WfcT[i] = Wfc[(size_t)d * H + k];
    }
    if (i0 == 0) g_bar = 0u;
}

// ---------------- xg GEMM: xg[t][r] = sum_k x[t][k] W_ih[r][k] + b ----------
__global__ void xg_kernel(const float* __restrict__ x,
                          const float* __restrict__ Wih,
                          const float* __restrict__ bih,
                          const float* __restrict__ bhh)
{
    __shared__ float As[64][68];   // [k][m], padded
    __shared__ float Bs[64][68];   // [k][n]
    const int tid = threadIdx.x;
    const int tx = tid & 15, ty = tid >> 4;
    const int t0 = blockIdx.y * 64, r0 = blockIdx.x * 64;

    float acc[4][4];
#pragma unroll
    for (int a = 0; a < 4; a++)
#pragma unroll
        for (int b = 0; b < 4; b++) acc[a][b] = 0.f;

    const int m  = tid >> 2;          // 0..63
    const int kb = (tid & 3) << 4;    // 0,16,32,48

    for (int k0 = 0; k0 < DIN; k0 += 64) {
#pragma unroll
        for (int q = 0; q < 4; q++) {
            float4 va = *(const float4*)(x   + (size_t)(t0 + m) * DIN + k0 + kb + q * 4);
            As[kb + q*4 + 0][m] = va.x; As[kb + q*4 + 1][m] = va.y;
            As[kb + q*4 + 2][m] = va.z; As[kb + q*4 + 3][m] = va.w;
            float4 vb = *(const float4*)(Wih + (size_t)(r0 + m) * DIN + k0 + kb + q * 4);
            Bs[kb + q*4 + 0][m] = vb.x; Bs[kb + q*4 + 1][m] = vb.y;
            Bs[kb + q*4 + 2][m] = vb.z; Bs[kb + q*4 + 3][m] = vb.w;
        }
        __syncthreads();
#pragma unroll
        for (int kk = 0; kk < 64; kk++) {
            float4 a4 = *(const float4*)&As[kk][ty * 4];
            float4 b4 = *(const float4*)&Bs[kk][tx * 4];
            acc[0][0] = fmaf(a4.x, b4.x, acc[0][0]);
            acc[0][1] = fmaf(a4.x, b4.y, acc[0][1]);
            acc[0][2] = fmaf(a4.x, b4.z, acc[0][2]);
            acc[0][3] = fmaf(a4.x, b4.w, acc[0][3]);
            acc[1][0] = fmaf(a4.y, b4.x, acc[1][0]);
            acc[1][1] = fmaf(a4.y, b4.y, acc[1][1]);
            acc[1][2] = fmaf(a4.y, b4.z, acc[1][2]);
            acc[1][3] = fmaf(a4.y, b4.w, acc[1][3]);
            acc[2][0] = fmaf(a4.z, b4.x, acc[2][0]);
            acc[2][1] = fmaf(a4.z, b4.y, acc[2][1]);
            acc[2][2] = fmaf(a4.z, b4.z, acc[2][2]);
            acc[2][3] = fmaf(a4.z, b4.w, acc[2][3]);
            acc[3][0] = fmaf(a4.w, b4.x, acc[3][0]);
            acc[3][1] = fmaf(a4.w, b4.y, acc[3][1]);
            acc[3][2] = fmaf(a4.w, b4.z, acc[3][2]);
            acc[3][3] = fmaf(a4.w, b4.w, acc[3][3]);
        }
        __syncthreads();
    }

    const int r = r0 + tx * 4;
    float b0 = bih[r + 0] + bhh[r + 0];
    float b1 = bih[r + 1] + bhh[r + 1];
    float b2 = bih[r + 2] + bhh[r + 2];
    float b3 = bih[r + 3] + bhh[r + 3];
#pragma unroll
    for (int mi = 0; mi < 4; mi++) {
        float4 o;
        o.x = acc[mi][0] + b0; o.y = acc[mi][1] + b1;
        o.z = acc[mi][2] + b2; o.w = acc[mi][3] + b3;
        *(float4*)(g_xg + (size_t)(t0 + ty * 4 + mi) * H4 + r) = o;
    }
}

// ---------------- persistent LSTM recurrence --------------------------------
__device__ __forceinline__ float sigm(float v) {
    return 1.f / (1.f + __expf(-v));
}

// one bf16x2 (2 weights) * one packed f32 h-pair -> packed f32x2 accumulator
#define FMA_BF2(W32, HP, ACC) do {                                          \
    unsigned _flo = (W32) << 16;                                            \
    unsigned _fhi = (W32) & 0xffff0000u;                                    \
    unsigned long long _wp;                                                 \
    asm("mov.b64 %0, {%1,%2};" : "=l"(_wp) : "r"(_flo), "r"(_fhi));         \
    asm("fma.rn.f32x2 %0, %1, %2, %0;" : "+l"(ACC) : "l"(_wp), "l"(HP));    \
} while (0)

// one SMEM uint4 (8 bf16 weights) against h pairs hp0..hp3 (8 h values)
#define DOT_ROW(ROFF, ACC) do {                                             \
    uint4 _wv = *(const uint4*)(mysw + (ROFF) + k0);                        \
    FMA_BF2(_wv.x, hp0, ACC);                                               \
    FMA_BF2(_wv.y, hp1, ACC);                                               \
    FMA_BF2(_wv.z, hp2, ACC);                                               \
    FMA_BF2(_wv.w, hp3, ACC);                                               \
} while (0)

__global__ void __launch_bounds__(NTHR, 1)
lstm_kernel(const float* __restrict__ cprev, float* __restrict__ dout)
{
    extern __shared__ __nv_bfloat16 sw[];   // [nj*4][2048] bf16 gate rows
    const int cta = blockIdx.x;
    int jbase, nj;
    if (cta < 124) { nj = 14; jbase = cta * 14; }
    else           { nj = 13; jbase = 1736 + (cta - 124) * 13; }

    const int w = threadIdx.x >> 5;
    const int l = threadIdx.x & 31;

    // load this CTA's gate rows into SMEM (row layout: (jj*4+gate) * 2048)
    const int n16 = nj * 4 * 256;   // uint4 count
    for (int idx = threadIdx.x; idx < n16; idx += NTHR) {
        int row_local = idx >> 8;
        int k8 = idx & 255;
        int jj = row_local >> 2, gate = row_local & 3;
        int grow = gate * H + jbase + jj;
        ((uint4*)sw)[idx] = ((const uint4*)g_Whh)[(size_t)grow * 256 + k8];
    }

    const bool active = (w < nj);
    const int j = jbase + w;
    float c = 0.f, hkeep = 0.f;
    if (active && l == 0) c = cprev[j];
    __syncthreads();

    const __nv_bfloat16* mysw = sw + (size_t)(w * 4) * H;

    for (int t = 0; t < SEQ; t++) {
        const float* hb = g_hbuf[t & 1];
        unsigned long long acc0 = 0, acc1 = 0, acc2 = 0, acc3 = 0;
        float xgv = 0.f;

        if (active) {
            if (l < 4) xgv = __ldg(&g_xg[(size_t)t * H4 + l * H + j]);
#pragma unroll
            for (int i = 0; i < 8; i++) {
                const int k0 = (i << 8) + (l << 3);
                unsigned long long hp0, hp1, hp2, hp3;
                // L1-bypassing packed loads: {h[k0],h[k0+1]} etc.
                asm("ld.global.cg.v2.u64 {%0,%1}, [%2];"
                    : "=l"(hp0), "=l"(hp1) : "l"(hb + k0));
                asm("ld.global.cg.v2.u64 {%0,%1}, [%2];"
                    : "=l"(hp2), "=l"(hp3) : "l"(hb + k0 + 4));
                DOT_ROW(0,        acc0);
                DOT_ROW(1 * 2048, acc1);
                DOT_ROW(2 * 2048, acc2);
                DOT_ROW(3 * 2048, acc3);
            }
            unsigned lo, hi;
            float a0, a1, a2, a3;
            asm("mov.b64 {%0,%1}, %2;" : "=r"(lo), "=r"(hi) : "l"(acc0));
            a0 = __uint_as_float(lo) + __uint_as_float(hi);
            asm("mov.b64 {%0,%1}, %2;" : "=r"(lo), "=r"(hi) : "l"(acc1));
            a1 = __uint_as_float(lo) + __uint_as_float(hi);
            asm("mov.b64 {%0,%1}, %2;" : "=r"(lo), "=r"(hi) : "l"(acc2));
            a2 = __uint_as_float(lo) + __uint_as_float(hi);
            asm("mov.b64 {%0,%1}, %2;" : "=r"(lo), "=r"(hi) : "l"(acc3));
            a3 = __uint_as_float(lo) + __uint_as_float(hi);
#pragma unroll
            for (int off = 16; off > 0; off >>= 1) {
                a0 += __shfl_down_sync(0xffffffffu, a0, off);
                a1 += __shfl_down_sync(0xffffffffu, a1, off);
                a2 += __shfl_down_sync(0xffffffffu, a2, off);
                a3 += __shfl_down_sync(0xffffffffu, a3, off);
            }
            float x0 = __shfl_sync(0xffffffffu, xgv, 0);
            float x1 = __shfl_sync(0xffffffffu, xgv, 1);
            float x2 = __shfl_sync(0xffffffffu, xgv, 2);
            float x3 = __shfl_sync(0xffffffffu, xgv, 3);
            if (l == 0) {
                float zi = a0 + x0, zf = a1 + x1, zg = a2 + x2, zo = a3 + x3;
                float ig = sigm(zi);
                float fg = sigm(zf);
                float gg = tanhf(zg);
                float og = sigm(zo);
                c = fg * c + ig * gg;
                float hn = og * tanhf(c);
                hkeep = hn;
                g_hbuf[(t + 1) & 1][j] = hn;   // write-through to L2
                g_hs[(size_t)t * H + j] = hn;
            }
        }

        // ---- grid barrier: release-arrive / acquire-poll, no L1 flush ------
        __syncthreads();                       // all hb reads done, h writes issued
        if (threadIdx.x == 0) {
            asm volatile("red.release.gpu.global.add.u32 [%0], %1;"
                         :: "l"(&g_bar), "r"(1u) : "memory");
            const unsigned target = (unsigned)(t + 1) * (unsigned)NCTA;
            unsigned v;
            do {
                asm volatile("ld.acquire.gpu.global.u32 %0, [%1];"
                             : "=r"(v) : "l"(&g_bar) : "memory");
            } while (v < target);
        }
        __syncthreads();
    }

    if (active && l == 0) {
        dout[OUT_BASE + j]     = hkeep;   // hT
        dout[OUT_BASE + H + j] = c;       // cT
    }
}

// ---------------- output FC: out = sigmoid(hs @ W_fc^T + b_fc) --------------
__global__ void fc_kernel(const float* __restrict__ bfc, float* __restrict__ out)
{
    const int gw = (blockIdx.x * blockDim.x + threadIdx.x) >> 5;  // 0..4095
    const int l  = threadIdx.x & 31;
    const int t0 = gw * 2;

    float ax0 = 0.f, ay0 = 0.f, ax1 = 0.f, ay1 = 0.f;
    const float* hs0 = g_hs + (size_t)t0 * H;

#pragma unroll 8
    for (int k = 0; k < H; k++) {
        float2 wv = *(const float2*)(g_WfcT + k * DOUT + 2 * l);
        float h0 = __ldg(hs0 + k);
        float h1 = __ldg(hs0 + H + k);
        ax0 = fmaf(h0, wv.x, ax0); ay0 = fmaf(h0, wv.y, ay0);
        ax1 = fmaf(h1, wv.x, ax1); ay1 = fmaf(h1, wv.y, ay1);
    }
    const float bx = bfc[2 * l], by = bfc[2 * l + 1];
    float2 o;
    o.x = sigm(ax0 + bx); o.y = sigm(ay0 + by);
    *(float2*)(out + (size_t)(t0 + 0) * DOUT + 2 * l) = o;
    o.x = sigm(ax1 + bx); o.y = sigm(ay1 + by);
    *(float2*)(out + (size_t)(t0 + 1) * DOUT + 2 * l) = o;
}

// ---------------- launch -----------------------------------------------------
extern "C" void kernel_launch(void* const* d_in, const int* in_sizes, int n_in,
                              void* d_out, int out_size)
{
    const float* x     = (const float*)d_in[0];
    const float* hprev = (const float*)d_in[1];
    const float* cprev = (const float*)d_in[2];
    const float* Wih   = (const float*)d_in[3];
    const float* Whh   = (const float*)d_in[4];
    const float* bih   = (const float*)d_in[5];
    const float* bhh   = (const float*)d_in[6];
    const float* Wfc   = (const float*)d_in[7];
    const float* bfc   = (const float*)d_in[8];
    float* out = (float*)d_out;

    cudaFuncSetAttribute(lstm_kernel,
                         cudaFuncAttributeMaxDynamicSharedMemorySize, 229376);

    prep_kernel<<<4096, 256>>>(Whh, hprev, Wfc);

    dim3 gg(H4 / 64, SEQ / 64);
    xg_kernel<<<gg, 256>>>(x, Wih, bih, bhh);

    lstm_kernel<<<NCTA, NTHR, 229376>>>(cprev, out);

    fc_kernel<<<512, 256>>>(bfc, out);
}

// round 4
// speedup vs baseline: 2.4701x; 2.4701x over previous
#include <cuda_runtime.h>
#include <cuda_bf16.h>

#define SEQ   8192
#define DIN   256
#define H     2048
#define H4    8192
#define DOUT  64
#define NCTA  148
#define NTHR  448   // 14 warps
#define OUT_BASE (SEQ * DOUT)   // 524288

#define SW_ITERS 12   // k-iterations (of 16) whose weights live in SMEM
#define RW_ITERS 4    // k-iterations whose weights live in registers

// ---------------- device scratch (allowed: __device__ globals) --------------
__device__ __nv_bfloat16 g_Whh[(size_t)H4 * H]; // 33.5 MB bf16 W_hh
__device__ float   g_xg [(size_t)SEQ * H4];     // 256 MB  x @ W_ih^T + b
__device__ float   g_hs [(size_t)SEQ * H];      // 64 MB   h history
__device__ float   g_hbuf[2][H];                // double-buffered h
__device__ float   g_WfcT[H * DOUT];            // W_fc transposed [k][d]
__device__ unsigned g_bar;                      // cumulative grid barrier

// ---------------- prep: bf16 convert, transpose, init ----------------------
__global__ void prep_kernel(const float* __restrict__ Whh,
                            const float* __restrict__ hprev,
                            const float* __restrict__ Wfc)
{
    size_t stride = (size_t)gridDim.x * blockDim.x;
    size_t i0 = (size_t)blockIdx.x * blockDim.x + threadIdx.x;
    const size_t npair = (size_t)H4 * H / 2;
    for (size_t p = i0; p < npair; p += stride) {
        float2 v = ((const float2*)Whh)[p];
        ((__nv_bfloat162*)g_Whh)[p] = __floats2bfloat162_rn(v.x, v.y);
    }
    for (size_t i = i0; i < H; i += stride)
        g_hbuf[0][i] = hprev[i];
    for (size_t i = i0; i < (size_t)H * DOUT; i += stride) {
        int d = (int)(i & (DOUT - 1));
        int k = (int)(i >> 6);
        g_WfcT[i] = Wfc[(size_t)d * H + k];
    }
    if (i0 == 0) g_bar = 0u;
}

// ---------------- xg GEMM: xg[t][r] = sum_k x[t][k] W_ih[r][k] + b ----------
__global__ void xg_kernel(const float* __restrict__ x,
                          const float* __restrict__ Wih,
                          const float* __restrict__ bih,
                          const float* __restrict__ bhh)
{
    __shared__ float As[64][68];
    __shared__ float Bs[64][68];
    const int tid = threadIdx.x;
    const int tx = tid & 15, ty = tid >> 4;
    const int t0 = blockIdx.y * 64, r0 = blockIdx.x * 64;

    float acc[4][4];
#pragma unroll
    for (int a = 0; a < 4; a++)
#pragma unroll
        for (int b = 0; b < 4; b++) acc[a][b] = 0.f;

    const int m  = tid >> 2;
    const int kb = (tid & 3) << 4;

    for (int k0 = 0; k0 < DIN; k0 += 64) {
#pragma unroll
        for (int q = 0; q < 4; q++) {
            float4 va = *(const float4*)(x   + (size_t)(t0 + m) * DIN + k0 + kb + q * 4);
            As[kb + q*4 + 0][m] = va.x; As[kb + q*4 + 1][m] = va.y;
            As[kb + q*4 + 2][m] = va.z; As[kb + q*4 + 3][m] = va.w;
            float4 vb = *(const float4*)(Wih + (size_t)(r0 + m) * DIN + k0 + kb + q * 4);
            Bs[kb + q*4 + 0][m] = vb.x; Bs[kb + q*4 + 1][m] = vb.y;
            Bs[kb + q*4 + 2][m] = vb.z; Bs[kb + q*4 + 3][m] = vb.w;
        }
        __syncthreads();
#pragma unroll
        for (int kk = 0; kk < 64; kk++) {
            float4 a4 = *(const float4*)&As[kk][ty * 4];
            float4 b4 = *(const float4*)&Bs[kk][tx * 4];
            acc[0][0] = fmaf(a4.x, b4.x, acc[0][0]);
            acc[0][1] = fmaf(a4.x, b4.y, acc[0][1]);
            acc[0][2] = fmaf(a4.x, b4.z, acc[0][2]);
            acc[0][3] = fmaf(a4.x, b4.w, acc[0][3]);
            acc[1][0] = fmaf(a4.y, b4.x, acc[1][0]);
            acc[1][1] = fmaf(a4.y, b4.y, acc[1][1]);
            acc[1][2] = fmaf(a4.y, b4.z, acc[1][2]);
            acc[1][3] = fmaf(a4.y, b4.w, acc[1][3]);
            acc[2][0] = fmaf(a4.z, b4.x, acc[2][0]);
            acc[2][1] = fmaf(a4.z, b4.y, acc[2][1]);
            acc[2][2] = fmaf(a4.z, b4.z, acc[2][2]);
            acc[2][3] = fmaf(a4.z, b4.w, acc[2][3]);
            acc[3][0] = fmaf(a4.w, b4.x, acc[3][0]);
            acc[3][1] = fmaf(a4.w, b4.y, acc[3][1]);
            acc[3][2] = fmaf(a4.w, b4.z, acc[3][2]);
            acc[3][3] = fmaf(a4.w, b4.w, acc[3][3]);
        }
        __syncthreads();
    }

    const int r = r0 + tx * 4;
    float b0 = bih[r + 0] + bhh[r + 0];
    float b1 = bih[r + 1] + bhh[r + 1];
    float b2 = bih[r + 2] + bhh[r + 2];
    float b3 = bih[r + 3] + bhh[r + 3];
#pragma unroll
    for (int mi = 0; mi < 4; mi++) {
        float4 o;
        o.x = acc[mi][0] + b0; o.y = acc[mi][1] + b1;
        o.z = acc[mi][2] + b2; o.w = acc[mi][3] + b3;
        *(float4*)(g_xg + (size_t)(t0 + ty * 4 + mi) * H4 + r) = o;
    }
}

// ---------------- persistent LSTM recurrence --------------------------------
__device__ __forceinline__ float sigm(float v) {
    return 1.f / (1.f + __expf(-v));
}

// bf16 pair (packed in u32: elem k low, elem k+1 high) expanded via cheap ALU
#define BF_LO(u) __uint_as_float((u) << 16)
#define BF_HI(u) __uint_as_float((u) & 0xffff0000u)

// accumulate 4 weights (uint2 = 4 bf16) * 4 h values (float4)
#define ACC4(A, W, HV) do {                         \
    A = fmaf(BF_LO((W).x), (HV).x, A);              \
    A = fmaf(BF_HI((W).x), (HV).y, A);              \
    A = fmaf(BF_LO((W).y), (HV).z, A);              \
    A = fmaf(BF_HI((W).y), (HV).w, A);              \
} while (0)

__global__ void __launch_bounds__(NTHR, 1)
lstm_kernel(const float* __restrict__ cprev, float* __restrict__ dout)
{
    // SMEM: [0, 172032) bf16 weights as uint2; [172032, 180224) staged h
    extern __shared__ unsigned char smem_raw[];
    uint2* sw  = (uint2*)smem_raw;
    float* shh = (float*)(smem_raw + 14 * SW_ITERS * 4 * 32 * 8);

    const int cta = blockIdx.x;
    int jbase, nj;
    if (cta < 124) { nj = 14; jbase = cta * 14; }
    else           { nj = 13; jbase = 1736 + (cta - 124) * 13; }

    const int w = threadIdx.x >> 5;
    const int l = threadIdx.x & 31;
    const bool active = (w < nj);
    const int j = jbase + w;

    // ---- stage SMEM weights: layout ((w*12 + i)*4 + row)*32 + l, uint2 each
    const int tot = nj * SW_ITERS * 4 * 32;
    for (int idx = threadIdx.x; idx < tot; idx += NTHR) {
        int l2  = idx & 31;
        int row = (idx >> 5) & 3;
        int i   = (idx >> 7) % SW_ITERS;
        int ww  = idx / (SW_ITERS * 4 * 32);
        size_t src = ((size_t)(row * H + jbase + ww) * 2048 + (size_t)i * 128 + l2 * 4) >> 2;
        sw[idx] = ((const uint2*)g_Whh)[src];
    }

    // ---- register-resident weights: iterations 12..15
    uint2 rw[RW_ITERS][4];
    if (active) {
#pragma unroll
        for (int i2 = 0; i2 < RW_ITERS; i2++)
#pragma unroll
            for (int r = 0; r < 4; r++)
                rw[i2][r] = ((const uint2*)g_Whh)[
                    ((size_t)(r * H + j) * 2048 + (size_t)(SW_ITERS + i2) * 128 + l * 4) >> 2];
    }

    float c = 0.f, hkeep = 0.f;
    if (active && l == 0) c = cprev[j];
    __syncthreads();

    const uint2* wp = sw + (size_t)w * SW_ITERS * 4 * 32 + l;

    for (int t = 0; t < SEQ; t++) {
        // ---- stage h into SMEM (L1-bypassing loads for cross-SM coherence)
        const float4* hb4 = (const float4*)g_hbuf[t & 1];
        for (int idx = threadIdx.x; idx < 512; idx += NTHR)
            ((float4*)shh)[idx] = __ldcg(hb4 + idx);

        float xgv = 0.f;
        if (active && l < 4)
            xgv = __ldg(&g_xg[(size_t)t * H4 + l * H + j]);
        __syncthreads();

        float a0 = 0.f, a1 = 0.f, a2 = 0.f, a3 = 0.f;
        if (active) {
#pragma unroll
            for (int i = 0; i < SW_ITERS; i++) {
                float4 hv = *(const float4*)(shh + i * 128 + l * 4);
                uint2 w0 = wp[i * 128 +  0];
                uint2 w1 = wp[i * 128 + 32];
                uint2 w2 = wp[i * 128 + 64];
                uint2 w3 = wp[i * 128 + 96];
                ACC4(a0, w0, hv);
                ACC4(a1, w1, hv);
                ACC4(a2, w2, hv);
                ACC4(a3, w3, hv);
            }
#pragma unroll
            for (int i2 = 0; i2 < RW_ITERS; i2++) {
                float4 hv = *(const float4*)(shh + (SW_ITERS + i2) * 128 + l * 4);
                ACC4(a0, rw[i2][0], hv);
                ACC4(a1, rw[i2][1], hv);
                ACC4(a2, rw[i2][2], hv);
                ACC4(a3, rw[i2][3], hv);
            }
#pragma unroll
            for (int off = 16; off > 0; off >>= 1) {
                a0 += __shfl_down_sync(0xffffffffu, a0, off);
                a1 += __shfl_down_sync(0xffffffffu, a1, off);
                a2 += __shfl_down_sync(0xffffffffu, a2, off);
                a3 += __shfl_down_sync(0xffffffffu, a3, off);
            }
            float x0 = __shfl_sync(0xffffffffu, xgv, 0);
            float x1 = __shfl_sync(0xffffffffu, xgv, 1);
            float x2 = __shfl_sync(0xffffffffu, xgv, 2);
            float x3 = __shfl_sync(0xffffffffu, xgv, 3);
            if (l == 0) {
                float ig = sigm(a0 + x0);
                float fg = sigm(a1 + x1);
                float gg = tanhf(a2 + x2);
                float og = sigm(a3 + x3);
                c = fg * c + ig * gg;
                float hn = og * tanhf(c);
                hkeep = hn;
                g_hbuf[(t + 1) & 1][j] = hn;
                g_hs[(size_t)t * H + j] = hn;
            }
        }

        // ---- grid barrier: release-arrive / acquire-poll ------------------
        __syncthreads();
        if (threadIdx.x == 0) {
            asm volatile("red.release.gpu.global.add.u32 [%0], %1;"
                         :: "l"(&g_bar), "r"(1u) : "memory");
            const unsigned target = (unsigned)(t + 1) * (unsigned)NCTA;
            unsigned v;
            do {
                asm volatile("ld.acquire.gpu.global.u32 %0, [%1];"
                             : "=r"(v) : "l"(&g_bar) : "memory");
            } while (v < target);
        }
        __syncthreads();
    }

    if (active && l == 0) {
        dout[OUT_BASE + j]     = hkeep;   // hT
        dout[OUT_BASE + H + j] = c;       // cT
    }
}

// ---------------- output FC: out = sigmoid(hs @ W_fc^T + b_fc) --------------
__global__ void fc_kernel(const float* __restrict__ bfc, float* __restrict__ out)
{
    const int gw = (blockIdx.x * blockDim.x + threadIdx.x) >> 5;  // 0..4095
    const int l  = threadIdx.x & 31;
    const int t0 = gw * 2;

    float ax0 = 0.f, ay0 = 0.f, ax1 = 0.f, ay1 = 0.f;
    const float* hs0 = g_hs + (size_t)t0 * H;

#pragma unroll 8
    for (int k = 0; k < H; k++) {
        float2 wv = *(const float2*)(g_WfcT + k * DOUT + 2 * l);
        float h0 = __ldg(hs0 + k);
        float h1 = __ldg(hs0 + H + k);
        ax0 = fmaf(h0, wv.x, ax0); ay0 = fmaf(h0, wv.y, ay0);
        ax1 = fmaf(h1, wv.x, ax1); ay1 = fmaf(h1, wv.y, ay1);
    }
    const float bx = bfc[2 * l], by = bfc[2 * l + 1];
    float2 o;
    o.x = sigm(ax0 + bx); o.y = sigm(ay0 + by);
    *(float2*)(out + (size_t)(t0 + 0) * DOUT + 2 * l) = o;
    o.x = sigm(ax1 + bx); o.y = sigm(ay1 + by);
    *(float2*)(out + (size_t)(t0 + 1) * DOUT + 2 * l) = o;
}

// ---------------- launch -----------------------------------------------------
extern "C" void kernel_launch(void* const* d_in, const int* in_sizes, int n_in,
                              void* d_out, int out_size)
{
    const float* x     = (const float*)d_in[0];
    const float* hprev = (const float*)d_in[1];
    const float* cprev = (const float*)d_in[2];
    const float* Wih   = (const float*)d_in[3];
    const float* Whh   = (const float*)d_in[4];
    const float* bih   = (const float*)d_in[5];
    const float* bhh   = (const float*)d_in[6];
    const float* Wfc   = (const float*)d_in[7];
    const float* bfc   = (const float*)d_in[8];
    float* out = (float*)d_out;

    const int smem_bytes = 14 * SW_ITERS * 4 * 32 * 8 + 2048 * 4;  // 180224
    cudaFuncSetAttribute(lstm_kernel,
                         cudaFuncAttributeMaxDynamicSharedMemorySize, smem_bytes);

    prep_kernel<<<4096, 256>>>(Whh, hprev, Wfc);

    dim3 gg(H4 / 64, SEQ / 64);
    xg_kernel<<<gg, 256>>>(x, Wih, bih, bhh);

    lstm_kernel<<<NCTA, NTHR, smem_bytes>>>(cprev, out);

    fc_kernel<<<512, 256>>>(bfc, out);
}